// round 2
// baseline (speedup 1.0000x reference)
#include <cuda_runtime.h>
#include <math.h>

// Problem constants
#define BSZ   32
#define TD    64
#define TEC   128
#define EDIM  256
#define HDIM  512
#define G4    2048          // 4*H
#define VOC   32000
#define KCH   8             // K-split chunks for the per-step LSTM GEMM
#define M_BT  2048          // BSZ*TD

// Scratch (device globals: no allocation allowed in kernel_launch)
__device__ float g_bias[G4];                 // b_ih + b_hh
__device__ float g_emb [M_BT * EDIM];        // gathered embeddings, row m = t*B + b
__device__ float g_xih [TD * BSZ * G4];      // X_ih (+bias) per (t,b)
__device__ float g_part[KCH * BSZ * G4];     // K-split partials of h @ W_hh^T (one step)
__device__ float g_hs  [TD * BSZ * HDIM];    // h_t for all steps, [t][b][h]
__device__ float g_c   [BSZ * HDIM];         // running cell state
__device__ float g_cat [M_BT * 2 * HDIM];    // [h ; ctx], row m = b*TD + t
__device__ float g_aout[M_BT * HDIM];        // tanh(attn) output

__device__ __forceinline__ float sigf(float x) { return 1.0f / (1.0f + expf(-x)); }

// ---------------------------------------------------------------------------
// bias = b_ih + b_hh
__global__ void k_bias(const float* __restrict__ bih, const float* __restrict__ bhh) {
    int i = blockIdx.x * 256 + threadIdx.x;
    if (i < G4) g_bias[i] = bih[i] + bhh[i];
}

// Embedding gather: g_emb[m][e], m = t*B + b. emb_W row 0 is already zero (padding).
__global__ void k_embed(const int* __restrict__ decX, const float* __restrict__ embW) {
    int m = blockIdx.x;            // 0..2047
    int e = threadIdx.x;           // 0..255
    int b = m & (BSZ - 1);
    int t = m >> 5;                // m / BSZ
    int tok = decX[b * TD + t];
    g_emb[m * EDIM + e] = embW[tok * EDIM + e];
}

// ---------------------------------------------------------------------------
// Generic fp32 GEMM: C[M,N] = act( A[M,K] * B[N,K]^T + bias[N] )
// M,N multiples of 128; K multiple of 8. act: 0=none, 1=tanh.
__global__ __launch_bounds__(256, 2)
void k_sgemm(const float* __restrict__ A, const float* __restrict__ Bm,
             const float* __restrict__ bias, float* __restrict__ C,
             int M, int N, int K, int act) {
    __shared__ float As[8][132];
    __shared__ float Bs[8][132];
    int tid = threadIdx.x;
    int m0 = blockIdx.y * 128, n0 = blockIdx.x * 128;

    int lr = tid >> 1;             // 0..127
    int lc = (tid & 1) * 4;        // 0 or 4
    const float* Ap = A + (size_t)(m0 + lr) * K + lc;
    const float* Bp = Bm + (size_t)(n0 + lr) * K + lc;

    int tx = tid & 15, ty = tid >> 4;
    float acc[8][8] = {};

    for (int kt = 0; kt < K; kt += 8) {
        float4 av = *(const float4*)(Ap + kt);
        float4 bv = *(const float4*)(Bp + kt);
        As[lc + 0][lr] = av.x; As[lc + 1][lr] = av.y;
        As[lc + 2][lr] = av.z; As[lc + 3][lr] = av.w;
        Bs[lc + 0][lr] = bv.x; Bs[lc + 1][lr] = bv.y;
        Bs[lc + 2][lr] = bv.z; Bs[lc + 3][lr] = bv.w;
        __syncthreads();
#pragma unroll
        for (int k = 0; k < 8; k++) {
            float a[8], bb[8];
#pragma unroll
            for (int i = 0; i < 8; i++) a[i] = As[k][ty * 8 + i];
#pragma unroll
            for (int j = 0; j < 8; j++) bb[j] = Bs[k][tx * 8 + j];
#pragma unroll
            for (int i = 0; i < 8; i++)
#pragma unroll
                for (int j = 0; j < 8; j++) acc[i][j] += a[i] * bb[j];
        }
        __syncthreads();
    }

#pragma unroll
    for (int i = 0; i < 8; i++) {
        int m = m0 + ty * 8 + i;
#pragma unroll
        for (int j = 0; j < 8; j++) {
            int n = n0 + tx * 8 + j;
            float v = acc[i][j] + bias[n];
            if (act) v = tanhf(v);
            C[(size_t)m * N + n] = v;
        }
    }
}

// ---------------------------------------------------------------------------
// Per-step LSTM GEMM, K-split: g_part[kc][b][j] = sum_{k in chunk} h[b,k]*W_hh[j,k]
// grid (16 j-tiles, 8 k-chunks), 256 threads, 4x4 per-thread micro-tile.
__global__ void k_ls(int t, const float* __restrict__ h0, const float* __restrict__ Whh) {
    __shared__ float hS[64][33];
    __shared__ float wS[64][129];
    int jt = blockIdx.x, kc = blockIdx.y;
    int tid = threadIdx.x;
    const float* hprev = (t == 0) ? h0 : (g_hs + (size_t)(t - 1) * BSZ * HDIM);
    int k0 = kc * 64;

#pragma unroll
    for (int r = 0; r < 8; r++) {        // 32 b x 64 k
        int li = r * 256 + tid;
        int b = li >> 6, k = li & 63;
        hS[k][b] = hprev[b * HDIM + k0 + k];
    }
#pragma unroll
    for (int r = 0; r < 32; r++) {       // 128 j x 64 k
        int li = r * 256 + tid;
        int j = li >> 6, k = li & 63;
        wS[k][j] = Whh[(size_t)(jt * 128 + j) * HDIM + k0 + k];
    }
    __syncthreads();

    int tx = tid & 31, ty = tid >> 5;    // tx: 32 j-groups of 4, ty: 8 b-groups of 4
    float acc[4][4] = {};
#pragma unroll
    for (int k = 0; k < 64; k++) {
        float hv[4], wv[4];
#pragma unroll
        for (int i = 0; i < 4; i++) hv[i] = hS[k][ty * 4 + i];
#pragma unroll
        for (int j = 0; j < 4; j++) wv[j] = wS[k][tx * 4 + j];
#pragma unroll
        for (int i = 0; i < 4; i++)
#pragma unroll
            for (int j = 0; j < 4; j++) acc[i][j] += hv[i] * wv[j];
    }
#pragma unroll
    for (int i = 0; i < 4; i++)
#pragma unroll
        for (int j = 0; j < 4; j++)
            g_part[(size_t)(kc * BSZ + ty * 4 + i) * G4 + jt * 128 + tx * 4 + j] = acc[i][j];
}

// Per-step pointwise LSTM update (sums the K-split partials deterministically)
__global__ void k_pw(int t, const float* __restrict__ c0) {
    int i = blockIdx.x * 256 + threadIdx.x;     // < BSZ*HDIM
    int b = i >> 9, h = i & 511;
    size_t base = (size_t)(t * BSZ + b) * G4 + h;
    float gi = g_xih[base];
    float gf = g_xih[base + HDIM];
    float gg = g_xih[base + 2 * HDIM];
    float go = g_xih[base + 3 * HDIM];
#pragma unroll
    for (int kc = 0; kc < KCH; kc++) {
        size_t pb = (size_t)(kc * BSZ + b) * G4 + h;
        gi += g_part[pb];
        gf += g_part[pb + HDIM];
        gg += g_part[pb + 2 * HDIM];
        go += g_part[pb + 3 * HDIM];
    }
    float cp = (t == 0) ? c0[i] : g_c[i];
    float c = sigf(gf) * cp + sigf(gi) * tanhf(gg);
    float hh = sigf(go) * tanhf(c);
    g_c[i] = c;
    g_hs[(size_t)t * BSZ * HDIM + i] = hh;
}

// ---------------------------------------------------------------------------
// Batched attention: block = (b, group of 8 t). Computes scores, softmax,
// context, and writes cat = [h ; ctx] in row order m = b*TD + t.
__global__ void k_attn(const float* __restrict__ enc) {
    __shared__ float hS[8][HDIM];
    __shared__ float sS[8][TEC];
    int bi = blockIdx.x;
    int b = bi >> 3;
    int t0 = (bi & 7) * 8;
    int tid = threadIdx.x;
    int w = tid >> 5, lane = tid & 31;

#pragma unroll
    for (int r = 0; r < 16; r++) {           // 8 tt x 512 h
        int li = r * 256 + tid;
        int tt = li >> 9, k = li & 511;
        hS[tt][k] = g_hs[(size_t)((t0 + tt) * BSZ + b) * HDIM + k];
    }
    __syncthreads();

    // scores: warp w handles te = w, w+8, ... (coalesced enc reads, 8 tt at once)
    for (int te = w; te < TEC; te += 8) {
        const float* ep = enc + (size_t)(b * TEC + te) * HDIM;
        float a8[8] = {};
        for (int k = lane; k < HDIM; k += 32) {
            float e = ep[k];
#pragma unroll
            for (int tt = 0; tt < 8; tt++) a8[tt] += e * hS[tt][k];
        }
#pragma unroll
        for (int tt = 0; tt < 8; tt++) {
            float v = a8[tt];
#pragma unroll
            for (int off = 16; off; off >>= 1) v += __shfl_xor_sync(0xffffffffu, v, off);
            if (lane == 0) sS[tt][te] = v;
        }
    }
    __syncthreads();

    // softmax over te (128) — warp per row
    {
        int row = w;
        float sv[4], mx = -1e30f;
#pragma unroll
        for (int q = 0; q < 4; q++) { sv[q] = sS[row][lane + 32 * q]; mx = fmaxf(mx, sv[q]); }
#pragma unroll
        for (int off = 16; off; off >>= 1) mx = fmaxf(mx, __shfl_xor_sync(0xffffffffu, mx, off));
        float sum = 0.0f;
#pragma unroll
        for (int q = 0; q < 4; q++) { sv[q] = expf(sv[q] - mx); sum += sv[q]; }
#pragma unroll
        for (int off = 16; off; off >>= 1) sum += __shfl_xor_sync(0xffffffffu, sum, off);
        float inv = 1.0f / sum;
#pragma unroll
        for (int q = 0; q < 4; q++) sS[row][lane + 32 * q] = sv[q] * inv;
    }
    __syncthreads();

    // context + cat writes
    for (int jj = tid; jj < HDIM; jj += 256) {
        float a8[8] = {};
        for (int te = 0; te < TEC; te++) {
            float e = enc[(size_t)(b * TEC + te) * HDIM + jj];
#pragma unroll
            for (int tt = 0; tt < 8; tt++) a8[tt] += sS[tt][te] * e;
        }
#pragma unroll
        for (int tt = 0; tt < 8; tt++) {
            int m = b * TD + t0 + tt;
            g_cat[(size_t)m * (2 * HDIM) + jj] = hS[tt][jj];
            g_cat[(size_t)m * (2 * HDIM) + HDIM + jj] = a8[tt];
        }
    }
}

// Final (h, c) tail: output tuple layout = [logits B*T*V][h B*H][c B*H]
__global__ void k_tail(float* __restrict__ out) {
    int i = blockIdx.x * 256 + threadIdx.x;
    if (i < BSZ * HDIM) {
        out[(size_t)M_BT * VOC + i] = g_hs[(size_t)(TD - 1) * BSZ * HDIM + i];
        out[(size_t)M_BT * VOC + BSZ * HDIM + i] = g_c[i];
    }
}

// ---------------------------------------------------------------------------
extern "C" void kernel_launch(void* const* d_in, const int* in_sizes, int n_in,
                              void* d_out, int out_size) {
    const int*   decX = (const int*)d_in[0];   // jax int64 demotes to int32 (x64 off)
    const float* enc  = (const float*)d_in[1];
    const float* h0   = (const float*)d_in[2];
    const float* c0   = (const float*)d_in[3];
    const float* embW = (const float*)d_in[4];
    const float* Wih  = (const float*)d_in[5];
    const float* Whh  = (const float*)d_in[6];
    const float* bih  = (const float*)d_in[7];
    const float* bhh  = (const float*)d_in[8];
    const float* attW = (const float*)d_in[9];
    const float* attb = (const float*)d_in[10];
    const float* fcW  = (const float*)d_in[11];
    const float* fcb  = (const float*)d_in[12];
    float* out = (float*)d_out;

    float *p_emb, *p_xih, *p_cat, *p_aout, *p_bias;
    cudaGetSymbolAddress((void**)&p_emb,  g_emb);
    cudaGetSymbolAddress((void**)&p_xih,  g_xih);
    cudaGetSymbolAddress((void**)&p_cat,  g_cat);
    cudaGetSymbolAddress((void**)&p_aout, g_aout);
    cudaGetSymbolAddress((void**)&p_bias, g_bias);

    k_bias<<<8, 256>>>(bih, bhh);
    k_embed<<<M_BT, 256>>>(decX, embW);
    // X_ih = emb @ W_ih^T + (b_ih + b_hh)   [2048 x 2048 x 256]
    k_sgemm<<<dim3(G4 / 128, M_BT / 128), 256>>>(p_emb, Wih, p_bias, p_xih,
                                                 M_BT, G4, EDIM, 0);
    // Sequential LSTM (recurrent state only — attention factored out)
    for (int t = 0; t < TD; t++) {
        k_ls<<<dim3(16, KCH), 256>>>(t, h0, Whh);
        k_pw<<<64, 256>>>(t, c0);
    }
    // Batched attention over all (b, t)
    k_attn<<<256, 256>>>(enc);
    // out = tanh(cat @ attn_W^T + attn_b)   [2048 x 512 x 1024]
    k_sgemm<<<dim3(HDIM / 128, M_BT / 128), 256>>>(p_cat, attW, attb, p_aout,
                                                   M_BT, HDIM, 2 * HDIM, 1);
    // logits = out @ fc_W^T + fc_b          [2048 x 32000 x 512]  (dominant)
    k_sgemm<<<dim3(VOC / 128, M_BT / 128), 256>>>(p_aout, fcW, fcb, out,
                                                  M_BT, VOC, HDIM, 0);
    k_tail<<<64, 256>>>(out);
}

// round 4
// speedup vs baseline: 1.6855x; 1.6855x over previous
#include <cuda_runtime.h>
#include <cuda_bf16.h>
#include <math.h>
#include <stdint.h>

// Problem constants
#define BSZ   32
#define TD    64
#define TEC   128
#define EDIM  256
#define HDIM  512
#define G4    2048
#define VOC   32000
#define KCH   8
#define M_BT  2048
#define KEXT  1536          // 3x512 split-bf16 extended K

// HMMA fc-GEMM tiling
#define BM    256
#define BN    128
#define BK    64
#define KI    (KEXT / BK)   // 24
#define ROWB  144           // padded SMEM row stride in bytes (64*2 + 16)
#define SA_BYTES (BM * ROWB)           // 36864
#define SB_BYTES (BN * ROWB)           // 18432
#define STAGE    (SA_BYTES + SB_BYTES) // 55296
#define NSTAGE   3
#define SM_TOTAL (NSTAGE * STAGE)      // 165888

// Scratch
__device__ float g_bias[G4];
__device__ float g_emb [M_BT * EDIM];
__device__ float g_xih [TD * BSZ * G4];
__device__ float g_part[KCH * BSZ * G4];
__device__ float g_hs  [TD * BSZ * HDIM];
__device__ float g_c   [BSZ * HDIM];
__device__ float g_cat [M_BT * 2 * HDIM];
__device__ float g_aout[M_BT * HDIM];
__device__ __align__(16) __nv_bfloat16 g_Aext[(size_t)M_BT * KEXT]; // [hi|hi|lo]
__device__ __align__(16) __nv_bfloat16 g_Bext[(size_t)VOC * KEXT];  // [hi|lo|hi]

__device__ __forceinline__ float sigf(float x) { return 1.0f / (1.0f + expf(-x)); }

__device__ __forceinline__ uint32_t smem_u32(const void* p) {
    uint32_t a;
    asm("{ .reg .u64 t; cvta.to.shared.u64 t, %1; cvt.u32.u64 %0, t; }" : "=r"(a) : "l"(p));
    return a;
}

// ---------------------------------------------------------------------------
__global__ void k_bias(const float* __restrict__ bih, const float* __restrict__ bhh) {
    int i = blockIdx.x * 256 + threadIdx.x;
    if (i < G4) g_bias[i] = bih[i] + bhh[i];
}

__global__ void k_embed(const int* __restrict__ decX, const float* __restrict__ embW) {
    int m = blockIdx.x;
    int e = threadIdx.x;
    int b = m & (BSZ - 1);
    int t = m >> 5;
    int tok = decX[b * TD + t];
    g_emb[m * EDIM + e] = embW[tok * EDIM + e];
}

// Generic fp32 GEMM (xih / attn): C = act(A[M,K]*B[N,K]^T + bias)
__global__ __launch_bounds__(256, 2)
void k_sgemm(const float* __restrict__ A, const float* __restrict__ Bm,
             const float* __restrict__ bias, float* __restrict__ C,
             int M, int N, int K, int act) {
    __shared__ float As[8][132];
    __shared__ float Bs[8][132];
    int tid = threadIdx.x;
    int m0 = blockIdx.y * 128, n0 = blockIdx.x * 128;
    int lr = tid >> 1;
    int lc = (tid & 1) * 4;
    const float* Ap = A + (size_t)(m0 + lr) * K + lc;
    const float* Bp = Bm + (size_t)(n0 + lr) * K + lc;
    int tx = tid & 15, ty = tid >> 4;
    float acc[8][8] = {};
    for (int kt = 0; kt < K; kt += 8) {
        float4 av = *(const float4*)(Ap + kt);
        float4 bv = *(const float4*)(Bp + kt);
        As[lc + 0][lr] = av.x; As[lc + 1][lr] = av.y;
        As[lc + 2][lr] = av.z; As[lc + 3][lr] = av.w;
        Bs[lc + 0][lr] = bv.x; Bs[lc + 1][lr] = bv.y;
        Bs[lc + 2][lr] = bv.z; Bs[lc + 3][lr] = bv.w;
        __syncthreads();
#pragma unroll
        for (int k = 0; k < 8; k++) {
            float a[8], bb[8];
#pragma unroll
            for (int i = 0; i < 8; i++) a[i] = As[k][ty * 8 + i];
#pragma unroll
            for (int j = 0; j < 8; j++) bb[j] = Bs[k][tx * 8 + j];
#pragma unroll
            for (int i = 0; i < 8; i++)
#pragma unroll
                for (int j = 0; j < 8; j++) acc[i][j] += a[i] * bb[j];
        }
        __syncthreads();
    }
#pragma unroll
    for (int i = 0; i < 8; i++) {
        int m = m0 + ty * 8 + i;
#pragma unroll
        for (int j = 0; j < 8; j++) {
            int n = n0 + tx * 8 + j;
            float v = acc[i][j] + bias[n];
            if (act) v = tanhf(v);
            C[(size_t)m * N + n] = v;
        }
    }
}

// ---------------------------------------------------------------------------
__global__ void k_ls(int t, const float* __restrict__ h0, const float* __restrict__ Whh) {
    __shared__ float hS[64][33];
    __shared__ float wS[64][129];
    int jt = blockIdx.x, kc = blockIdx.y;
    int tid = threadIdx.x;
    const float* hprev = (t == 0) ? h0 : (g_hs + (size_t)(t - 1) * BSZ * HDIM);
    int k0 = kc * 64;
#pragma unroll
    for (int r = 0; r < 8; r++) {
        int li = r * 256 + tid;
        int b = li >> 6, k = li & 63;
        hS[k][b] = hprev[b * HDIM + k0 + k];
    }
#pragma unroll
    for (int r = 0; r < 32; r++) {
        int li = r * 256 + tid;
        int j = li >> 6, k = li & 63;
        wS[k][j] = Whh[(size_t)(jt * 128 + j) * HDIM + k0 + k];
    }
    __syncthreads();
    int tx = tid & 31, ty = tid >> 5;
    float acc[4][4] = {};
#pragma unroll
    for (int k = 0; k < 64; k++) {
        float hv[4], wv[4];
#pragma unroll
        for (int i = 0; i < 4; i++) hv[i] = hS[k][ty * 4 + i];
#pragma unroll
        for (int j = 0; j < 4; j++) wv[j] = wS[k][tx * 4 + j];
#pragma unroll
        for (int i = 0; i < 4; i++)
#pragma unroll
            for (int j = 0; j < 4; j++) acc[i][j] += hv[i] * wv[j];
    }
#pragma unroll
    for (int i = 0; i < 4; i++)
#pragma unroll
        for (int j = 0; j < 4; j++)
            g_part[(size_t)(kc * BSZ + ty * 4 + i) * G4 + jt * 128 + tx * 4 + j] = acc[i][j];
}

__global__ void k_pw(int t, const float* __restrict__ c0) {
    int i = blockIdx.x * 256 + threadIdx.x;
    int b = i >> 9, h = i & 511;
    size_t base = (size_t)(t * BSZ + b) * G4 + h;
    float gi = g_xih[base];
    float gf = g_xih[base + HDIM];
    float gg = g_xih[base + 2 * HDIM];
    float go = g_xih[base + 3 * HDIM];
#pragma unroll
    for (int kc = 0; kc < KCH; kc++) {
        size_t pb = (size_t)(kc * BSZ + b) * G4 + h;
        gi += g_part[pb];
        gf += g_part[pb + HDIM];
        gg += g_part[pb + 2 * HDIM];
        go += g_part[pb + 3 * HDIM];
    }
    float cp = (t == 0) ? c0[i] : g_c[i];
    float c = sigf(gf) * cp + sigf(gi) * tanhf(gg);
    float hh = sigf(go) * tanhf(c);
    g_c[i] = c;
    g_hs[(size_t)t * BSZ * HDIM + i] = hh;
}

// ---------------------------------------------------------------------------
__global__ void k_attn(const float* __restrict__ enc) {
    __shared__ float hS[8][HDIM];
    __shared__ float sS[8][TEC];
    int bi = blockIdx.x;
    int b = bi >> 3;
    int t0 = (bi & 7) * 8;
    int tid = threadIdx.x;
    int w = tid >> 5, lane = tid & 31;
#pragma unroll
    for (int r = 0; r < 16; r++) {
        int li = r * 256 + tid;
        int tt = li >> 9, k = li & 511;
        hS[tt][k] = g_hs[(size_t)((t0 + tt) * BSZ + b) * HDIM + k];
    }
    __syncthreads();
    for (int te = w; te < TEC; te += 8) {
        const float* ep = enc + (size_t)(b * TEC + te) * HDIM;
        float a8[8] = {};
        for (int k = lane; k < HDIM; k += 32) {
            float e = ep[k];
#pragma unroll
            for (int tt = 0; tt < 8; tt++) a8[tt] += e * hS[tt][k];
        }
#pragma unroll
        for (int tt = 0; tt < 8; tt++) {
            float v = a8[tt];
#pragma unroll
            for (int off = 16; off; off >>= 1) v += __shfl_xor_sync(0xffffffffu, v, off);
            if (lane == 0) sS[tt][te] = v;
        }
    }
    __syncthreads();
    {
        int row = w;
        float sv[4], mx = -1e30f;
#pragma unroll
        for (int q = 0; q < 4; q++) { sv[q] = sS[row][lane + 32 * q]; mx = fmaxf(mx, sv[q]); }
#pragma unroll
        for (int off = 16; off; off >>= 1) mx = fmaxf(mx, __shfl_xor_sync(0xffffffffu, mx, off));
        float sum = 0.0f;
#pragma unroll
        for (int q = 0; q < 4; q++) { sv[q] = expf(sv[q] - mx); sum += sv[q]; }
#pragma unroll
        for (int off = 16; off; off >>= 1) sum += __shfl_xor_sync(0xffffffffu, sum, off);
        float inv = 1.0f / sum;
#pragma unroll
        for (int q = 0; q < 4; q++) sS[row][lane + 32 * q] = sv[q] * inv;
    }
    __syncthreads();
    for (int jj = tid; jj < HDIM; jj += 256) {
        float a8[8] = {};
        for (int te = 0; te < TEC; te++) {
            float e = enc[(size_t)(b * TEC + te) * HDIM + jj];
#pragma unroll
            for (int tt = 0; tt < 8; tt++) a8[tt] += sS[tt][te] * e;
        }
#pragma unroll
        for (int tt = 0; tt < 8; tt++) {
            int m = b * TD + t0 + tt;
            g_cat[(size_t)m * (2 * HDIM) + jj] = hS[tt][jj];
            g_cat[(size_t)m * (2 * HDIM) + HDIM + jj] = a8[tt];
        }
    }
}

__global__ void k_tail(float* __restrict__ out) {
    int i = blockIdx.x * 256 + threadIdx.x;
    if (i < BSZ * HDIM) {
        out[(size_t)M_BT * VOC + i] = g_hs[(size_t)(TD - 1) * BSZ * HDIM + i];
        out[(size_t)M_BT * VOC + BSZ * HDIM + i] = g_c[i];
    }
}

// ---------------------------------------------------------------------------
// Split-bf16 conversions: x = hi + lo
__global__ void k_cvt_a() {   // g_aout [2048x512] -> g_Aext [2048x1536] = [hi|hi|lo]
    size_t i = ((size_t)blockIdx.x * 256 + threadIdx.x) * 4;
    if (i >= (size_t)M_BT * HDIM) return;
    size_t m = i >> 9, k = i & 511;
    float4 x = *(const float4*)(g_aout + i);
    __nv_bfloat16 hi[4], lo[4];
    float xs[4] = {x.x, x.y, x.z, x.w};
#pragma unroll
    for (int q = 0; q < 4; q++) {
        hi[q] = __float2bfloat16(xs[q]);
        lo[q] = __float2bfloat16(xs[q] - __bfloat162float(hi[q]));
    }
    __nv_bfloat16* base = g_Aext + m * KEXT + k;
    *(uint2*)(base)        = *(uint2*)hi;
    *(uint2*)(base + 512)  = *(uint2*)hi;
    *(uint2*)(base + 1024) = *(uint2*)lo;
}

__global__ void k_cvt_b(const float* __restrict__ W) {  // fcW [32000x512] -> [hi|lo|hi]
    size_t i = ((size_t)blockIdx.x * 256 + threadIdx.x) * 4;
    if (i >= (size_t)VOC * HDIM) return;
    size_t n = i >> 9, k = i & 511;
    float4 x = *(const float4*)(W + i);
    __nv_bfloat16 hi[4], lo[4];
    float xs[4] = {x.x, x.y, x.z, x.w};
#pragma unroll
    for (int q = 0; q < 4; q++) {
        hi[q] = __float2bfloat16(xs[q]);
        lo[q] = __float2bfloat16(xs[q] - __bfloat162float(hi[q]));
    }
    __nv_bfloat16* base = g_Bext + n * KEXT + k;
    *(uint2*)(base)        = *(uint2*)hi;
    *(uint2*)(base + 512)  = *(uint2*)lo;
    *(uint2*)(base + 1024) = *(uint2*)hi;
}

// ---------------------------------------------------------------------------
// HMMA fc GEMM: C[2048,32000] = Aext @ Bext^T + fcb.
// mma.sync.m16n8k16 bf16, fp32 acc. CTA 256x128, 8 warps (4m x 2n), warp 64x64.
// 3-stage cp.async pipeline, padded SMEM rows (144B) for conflict-free ldmatrix.
__global__ __launch_bounds__(256, 1)
void k_hgemm(const float* __restrict__ fcb, float* __restrict__ C) {
    extern __shared__ char smem[];
    uint32_t sb = smem_u32(smem);
    int tid = threadIdx.x;
    int wid = tid >> 5, lane = tid & 31;
    int wm = wid & 3, wn = wid >> 2;       // warp tile: rows wm*64, cols wn*64
    int m0 = blockIdx.x * BM, n0 = blockIdx.y * BN;

    const __nv_bfloat16* gA0 = g_Aext + (size_t)m0 * KEXT;
    const __nv_bfloat16* gB0 = g_Bext + (size_t)n0 * KEXT;

    auto load_stage = [&](int kt, int s) {
        uint32_t sa = sb + s * STAGE;
        const __nv_bfloat16* gA = gA0 + kt * BK;
#pragma unroll
        for (int r8 = 0; r8 < 8; r8++) {            // A: 256 rows x 8 segs of 16B
            int li = r8 * 256 + tid;
            int row = li >> 3, seg = li & 7;
            uint32_t dst = sa + row * ROWB + seg * 16;
            const void* src = gA + (size_t)row * KEXT + seg * 8;
            asm volatile("cp.async.cg.shared.global [%0], [%1], 16;" :: "r"(dst), "l"(src));
        }
        uint32_t sbB = sa + SA_BYTES;
        const __nv_bfloat16* gB = gB0 + kt * BK;
#pragma unroll
        for (int r4 = 0; r4 < 4; r4++) {            // B: 128 rows x 8 segs
            int li = r4 * 256 + tid;
            int row = li >> 3, seg = li & 7;
            uint32_t dst = sbB + row * ROWB + seg * 16;
            const void* src = gB + (size_t)row * KEXT + seg * 8;
            asm volatile("cp.async.cg.shared.global [%0], [%1], 16;" :: "r"(dst), "l"(src));
        }
        asm volatile("cp.async.commit_group;" ::: "memory");
    };

    float acc[4][8][4];
#pragma unroll
    for (int i = 0; i < 4; i++)
#pragma unroll
        for (int j = 0; j < 8; j++)
#pragma unroll
            for (int q = 0; q < 4; q++) acc[i][j][q] = 0.0f;

    load_stage(0, 0);
    load_stage(1, 1);

    for (int kt = 0; kt < KI; kt++) {
        asm volatile("cp.async.wait_group 1;" ::: "memory");
        __syncthreads();
        int s = kt % NSTAGE;
        if (kt + 2 < KI) load_stage(kt + 2, (kt + 2) % NSTAGE);

        uint32_t sa = sb + s * STAGE;
        uint32_t sB = sa + SA_BYTES;
#pragma unroll
        for (int kk = 0; kk < 4; kk++) {
            uint32_t a[4][4], b[4][4];
#pragma unroll
            for (int i = 0; i < 4; i++) {
                int row = wm * 64 + i * 16 + (lane & 15);
                int ko = kk * 16 + ((lane >> 4) << 3);
                uint32_t ad = sa + row * ROWB + ko * 2;
                asm volatile("ldmatrix.sync.aligned.m8n8.x4.shared.b16 {%0,%1,%2,%3}, [%4];"
                             : "=r"(a[i][0]), "=r"(a[i][1]), "=r"(a[i][2]), "=r"(a[i][3])
                             : "r"(ad));
            }
#pragma unroll
            for (int j2 = 0; j2 < 4; j2++) {
                int nrow = wn * 64 + j2 * 16 + (lane & 7) + (((lane >> 4) & 1) << 3);
                int ko = kk * 16 + (((lane >> 3) & 1) << 3);
                uint32_t bd = sB + nrow * ROWB + ko * 2;
                asm volatile("ldmatrix.sync.aligned.m8n8.x4.shared.b16 {%0,%1,%2,%3}, [%4];"
                             : "=r"(b[j2][0]), "=r"(b[j2][1]), "=r"(b[j2][2]), "=r"(b[j2][3])
                             : "r"(bd));
            }
#pragma unroll
            for (int i = 0; i < 4; i++)
#pragma unroll
                for (int j2 = 0; j2 < 4; j2++) {
                    asm volatile(
                        "mma.sync.aligned.m16n8k16.row.col.f32.bf16.bf16.f32 "
                        "{%0,%1,%2,%3}, {%4,%5,%6,%7}, {%8,%9}, {%0,%1,%2,%3};"
                        : "+f"(acc[i][2*j2][0]), "+f"(acc[i][2*j2][1]),
                          "+f"(acc[i][2*j2][2]), "+f"(acc[i][2*j2][3])
                        : "r"(a[i][0]), "r"(a[i][1]), "r"(a[i][2]), "r"(a[i][3]),
                          "r"(b[j2][0]), "r"(b[j2][1]));
                    asm volatile(
                        "mma.sync.aligned.m16n8k16.row.col.f32.bf16.bf16.f32 "
                        "{%0,%1,%2,%3}, {%4,%5,%6,%7}, {%8,%9}, {%0,%1,%2,%3};"
                        : "+f"(acc[i][2*j2+1][0]), "+f"(acc[i][2*j2+1][1]),
                          "+f"(acc[i][2*j2+1][2]), "+f"(acc[i][2*j2+1][3])
                        : "r"(a[i][0]), "r"(a[i][1]), "r"(a[i][2]), "r"(a[i][3]),
                          "r"(b[j2][2]), "r"(b[j2][3]));
                }
        }
        __syncthreads();
    }
    asm volatile("cp.async.wait_group 0;" ::: "memory");

    // Epilogue: direct global stores with bias
#pragma unroll
    for (int j = 0; j < 8; j++) {
        int ncol = n0 + wn * 64 + j * 8 + (lane & 3) * 2;
        float b0 = fcb[ncol], b1 = fcb[ncol + 1];
#pragma unroll
        for (int i = 0; i < 4; i++) {
            int mrow = m0 + wm * 64 + i * 16 + (lane >> 2);
            float2 v0 = {acc[i][j][0] + b0, acc[i][j][1] + b1};
            float2 v1 = {acc[i][j][2] + b0, acc[i][j][3] + b1};
            *(float2*)(C + (size_t)mrow * VOC + ncol) = v0;
            *(float2*)(C + (size_t)(mrow + 8) * VOC + ncol) = v1;
        }
    }
}

// ---------------------------------------------------------------------------
extern "C" void kernel_launch(void* const* d_in, const int* in_sizes, int n_in,
                              void* d_out, int out_size) {
    const int*   decX = (const int*)d_in[0];
    const float* enc  = (const float*)d_in[1];
    const float* h0   = (const float*)d_in[2];
    const float* c0   = (const float*)d_in[3];
    const float* embW = (const float*)d_in[4];
    const float* Wih  = (const float*)d_in[5];
    const float* Whh  = (const float*)d_in[6];
    const float* bih  = (const float*)d_in[7];
    const float* bhh  = (const float*)d_in[8];
    const float* attW = (const float*)d_in[9];
    const float* attb = (const float*)d_in[10];
    const float* fcW  = (const float*)d_in[11];
    const float* fcb  = (const float*)d_in[12];
    float* out = (float*)d_out;

    float *p_emb, *p_xih, *p_cat, *p_aout, *p_bias;
    cudaGetSymbolAddress((void**)&p_emb,  g_emb);
    cudaGetSymbolAddress((void**)&p_xih,  g_xih);
    cudaGetSymbolAddress((void**)&p_cat,  g_cat);
    cudaGetSymbolAddress((void**)&p_aout, g_aout);
    cudaGetSymbolAddress((void**)&p_bias, g_bias);

    cudaFuncSetAttribute(k_hgemm, cudaFuncAttributeMaxDynamicSharedMemorySize, SM_TOTAL);

    // B-weight conversion first (independent of everything else)
    k_cvt_b<<<(VOC * HDIM / 4 + 255) / 256, 256>>>(fcW);

    k_bias<<<8, 256>>>(bih, bhh);
    k_embed<<<M_BT, 256>>>(decX, embW);
    k_sgemm<<<dim3(G4 / 128, M_BT / 128), 256>>>(p_emb, Wih, p_bias, p_xih,
                                                 M_BT, G4, EDIM, 0);
    for (int t = 0; t < TD; t++) {
        k_ls<<<dim3(16, KCH), 256>>>(t, h0, Whh);
        k_pw<<<64, 256>>>(t, c0);
    }
    k_attn<<<256, 256>>>(enc);
    k_sgemm<<<dim3(HDIM / 128, M_BT / 128), 256>>>(p_cat, attW, attb, p_aout,
                                                   M_BT, HDIM, 2 * HDIM, 1);
    // fc via HMMA tensor cores (split-bf16, K extended to 1536)
    k_cvt_a<<<(M_BT * HDIM / 4 + 255) / 256, 256>>>();
    k_hgemm<<<dim3(M_BT / BM, VOC / BN), 256, SM_TOTAL>>>(fcb, out);
    k_tail<<<64, 256>>>(out);
}